// round 14
// baseline (speedup 1.0000x reference)
#include <cuda_runtime.h>
#include <cuda_fp16.h>
#include <cstdint>

// ---------------------------------------------------------------------------
// Problem constants
// ---------------------------------------------------------------------------
#define ROWS_TOTAL 50176        // 256*14*14
#define KDIM       384
#define NDIM       1536
#define M_TILE     128
#define N_TILE     128
#define K_CHUNK    32
#define NUM_KC     (KDIM / K_CHUNK)   // 12
#define STAGES     3
#define LN_EPS     1e-6f

// fp16 scratch (no cudaMalloc allowed -> __device__ globals)
__device__ __half g_xh[(size_t)ROWS_TOTAL * KDIM];   // LN-applied X, fp16
__device__ __half g_wh[(size_t)NDIM * KDIM];         // W, fp16

// ---------------------------------------------------------------------------
// Inline PTX (baseline features only: ldmatrix / mma.sync / cp.async)
// ---------------------------------------------------------------------------
__device__ __forceinline__ uint32_t smem_u32(const void* p) {
    uint32_t a;
    asm("{ .reg .u64 t; cvta.to.shared.u64 t, %1; cvt.u32.u64 %0, t; }"
        : "=r"(a) : "l"(p));
    return a;
}

#define CP_ASYNC16(saddr, gptr) \
    asm volatile("cp.async.cg.shared.global [%0], [%1], 16;" \
                 :: "r"(saddr), "l"(gptr))

#define CP_COMMIT() asm volatile("cp.async.commit_group;")
#define CP_WAIT(n)  asm volatile("cp.async.wait_group %0;" :: "n"(n))

#define LDSM_X4(r, addr) \
    asm volatile("ldmatrix.sync.aligned.m8n8.x4.shared.b16 {%0,%1,%2,%3}, [%4];" \
                 : "=r"((r)[0]), "=r"((r)[1]), "=r"((r)[2]), "=r"((r)[3]) \
                 : "r"(addr))

#define MMA16816(c, a, b0v, b1v) \
    asm volatile("mma.sync.aligned.m16n8k16.row.col.f32.f16.f16.f32 " \
                 "{%0,%1,%2,%3}, {%4,%5,%6,%7}, {%8,%9}, {%0,%1,%2,%3};" \
                 : "+f"((c)[0]), "+f"((c)[1]), "+f"((c)[2]), "+f"((c)[3]) \
                 : "r"((a)[0]), "r"((a)[1]), "r"((a)[2]), "r"((a)[3]), \
                   "r"(b0v), "r"(b1v))

// ---------------------------------------------------------------------------
// SMEM: per stage { A [128][40] | B [128][40] }, 80B padded rows (conflict-free)
// ---------------------------------------------------------------------------
#define ROW_B      80
#define OFF_A      0
#define OFF_B      (M_TILE * ROW_B)               // 10240
#define STAGE_B    ((M_TILE + N_TILE) * ROW_B)    // 20480
#define SMEM_TOTAL (STAGES * STAGE_B)             // 61440 -> 3 CTAs/SM (184KB)

// Fast GELU: v * sigmoid(1.59577(v + 0.044715 v^3)) — branch-free, 2 MUFU.
__device__ __forceinline__ float gelu_fast(float v) {
    float t = v * v;
    float z = 1.5957691216f * v * fmaf(0.044715f, t, 1.0f);
    float e = __expf(-z);
    return __fdividef(v, 1.0f + e);
}

// ---------------------------------------------------------------------------
// Kernel 1: fused prepass. Blocks [0, 6272): LayerNorm -> fp16 X.
//           Blocks [6272, 6848): W fp32 -> fp16 convert.
// ---------------------------------------------------------------------------
#define LN_BLOCKS  (ROWS_TOTAL / 8)            // 6272
#define WC_BLOCKS  ((NDIM * KDIM) / 1024)      // 576

__global__ __launch_bounds__(256) void prepass_kernel(
    const float* __restrict__ x,
    const float* __restrict__ gamma,
    const float* __restrict__ beta,
    const float* __restrict__ W)
{
    if (blockIdx.x >= LN_BLOCKS) {
        int idx = ((blockIdx.x - LN_BLOCKS) * 256 + threadIdx.x) * 4;
        float4 wv = *reinterpret_cast<const float4*>(W + idx);
        __half2* p = reinterpret_cast<__half2*>(g_wh + idx);
        p[0] = __half2(__float2half_rn(wv.x), __float2half_rn(wv.y));
        p[1] = __half2(__float2half_rn(wv.z), __float2half_rn(wv.w));
        return;
    }

    int row  = blockIdx.x * 8 + (threadIdx.x >> 5);
    int lane = threadIdx.x & 31;
    const float4* xr = reinterpret_cast<const float4*>(x + (size_t)row * KDIM);

    float4 v[3];
    float s = 0.f, ss = 0.f;
#pragma unroll
    for (int i = 0; i < 3; i++) {
        v[i] = xr[lane + i * 32];
        s  += v[i].x + v[i].y + v[i].z + v[i].w;
        ss += v[i].x * v[i].x + v[i].y * v[i].y + v[i].z * v[i].z + v[i].w * v[i].w;
    }
#pragma unroll
    for (int o = 16; o > 0; o >>= 1) {
        s  += __shfl_xor_sync(0xffffffffu, s, o);
        ss += __shfl_xor_sync(0xffffffffu, ss, o);
    }
    float mu  = s * (1.0f / KDIM);
    float var = ss * (1.0f / KDIM) - mu * mu;
    float rs  = rsqrtf(var + LN_EPS);

#pragma unroll
    for (int i = 0; i < 3; i++) {
        int col = (lane + i * 32) * 4;
        float4 gv = *reinterpret_cast<const float4*>(gamma + col);
        float4 bv = *reinterpret_cast<const float4*>(beta + col);
        float n0 = fmaf(v[i].x - mu, rs * gv.x, bv.x);
        float n1 = fmaf(v[i].y - mu, rs * gv.y, bv.y);
        float n2 = fmaf(v[i].z - mu, rs * gv.z, bv.z);
        float n3 = fmaf(v[i].w - mu, rs * gv.w, bv.w);

        __half2* p = reinterpret_cast<__half2*>(g_xh + (size_t)row * KDIM + col);
        p[0] = __half2(__float2half_rn(n0), __float2half_rn(n1));
        p[1] = __half2(__float2half_rn(n2), __float2half_rn(n3));
    }
}

// ---------------------------------------------------------------------------
// Kernel 2: fp16 GEMM + bias + fast GELU
// CTA tile 128x128; 4 warps (128 thr), warp tile 64x64 (2M x 2N).
// Big square warp tiles: 8 LDSM.x4 feed 32 MMAs per k16 step
// (40% less smem-crossbar traffic per MAC than 32x48 warps).
// 3-stage cp.async pipeline, 3 CTAs/SM (12 warps).
// ---------------------------------------------------------------------------
__global__ __launch_bounds__(128, 3) void gemm_kernel(
    const float* __restrict__ bias,
    float* __restrict__ out)
{
    extern __shared__ char smem[];
    const uint32_t smem_base = smem_u32(smem);

    const int tid    = threadIdx.x;
    const int wid    = tid >> 5;
    const int lane   = tid & 31;
    const int warp_m = wid & 1;          // 0..1 (64-row halves)
    const int warp_n = wid >> 1;         // 0..1 (64-col halves)
    const int lrow   = lane & 15;
    const int lsel   = lane >> 4;

    const int n0 = blockIdx.x * N_TILE;  // n fastest -> X-tile L2 reuse
    const int m0 = blockIdx.y * M_TILE;

    // --- per-thread load pointers: thread t loads the full 64B k-row of
    //     A row t and B row t (4 x 16B cp.async each) ---
    const __half* pa = g_xh + (size_t)(m0 + tid) * KDIM;
    const __half* pb = g_wh + (size_t)(n0 + tid) * KDIM;
    const uint32_t soA = (uint32_t)(OFF_A + tid * ROW_B);
    const uint32_t soB = (uint32_t)(OFF_B + tid * ROW_B);

#define LOAD_STAGE(sb, k0)                                     \
    do {                                                       \
        CP_ASYNC16((sb) + soA,      pa + (k0));                \
        CP_ASYNC16((sb) + soA + 16, pa + (k0) + 8);            \
        CP_ASYNC16((sb) + soA + 32, pa + (k0) + 16);           \
        CP_ASYNC16((sb) + soA + 48, pa + (k0) + 24);           \
        CP_ASYNC16((sb) + soB,      pb + (k0));                \
        CP_ASYNC16((sb) + soB + 16, pb + (k0) + 8);            \
        CP_ASYNC16((sb) + soB + 32, pb + (k0) + 16);           \
        CP_ASYNC16((sb) + soB + 48, pb + (k0) + 24);           \
    } while (0)

    // --- hoisted ldmatrix base offsets ---
    uint32_t a_base[4], b_base[4];
#pragma unroll
    for (int mf = 0; mf < 4; mf++)
        a_base[mf] = (uint32_t)(OFF_A + (warp_m * 64 + mf * 16 + lrow) * ROW_B + lsel * 16);
#pragma unroll
    for (int nf2 = 0; nf2 < 4; nf2++)
        b_base[nf2] = (uint32_t)(OFF_B + (warp_n * 64 + nf2 * 16 + lrow) * ROW_B + lsel * 16);

    // prologue: prefetch STAGES-1 stages
#pragma unroll
    for (int s = 0; s < STAGES - 1; s++) {
        LOAD_STAGE(smem_base + s * STAGE_B, s * K_CHUNK);
        CP_COMMIT();
    }

    float acc[4][8][4];
#pragma unroll
    for (int a = 0; a < 4; a++)
#pragma unroll
        for (int b = 0; b < 8; b++)
#pragma unroll
            for (int c = 0; c < 4; c++) acc[a][b][c] = 0.f;

#pragma unroll
    for (int kc = 0; kc < NUM_KC; kc++) {
        CP_WAIT(STAGES - 2);
        __syncthreads();

        if (kc + STAGES - 1 < NUM_KC) {
            LOAD_STAGE(smem_base + ((kc + STAGES - 1) % STAGES) * STAGE_B,
                       (kc + STAGES - 1) * K_CHUNK);
        }
        CP_COMMIT();

        const uint32_t st = smem_base + (kc % STAGES) * STAGE_B;

#pragma unroll
        for (int ks = 0; ks < 2; ks++) {
            uint32_t af[4][4], bf[4][4];
#pragma unroll
            for (int nf2 = 0; nf2 < 4; nf2++)
                LDSM_X4(bf[nf2], st + b_base[nf2] + ks * 32);
#pragma unroll
            for (int mf = 0; mf < 4; mf++)
                LDSM_X4(af[mf], st + a_base[mf] + ks * 32);
#pragma unroll
            for (int mf = 0; mf < 4; mf++) {
#pragma unroll
                for (int nf = 0; nf < 8; nf++) {
                    const int g = nf >> 1, sel = nf & 1;
                    MMA16816(acc[mf][nf], af[mf], bf[g][sel], bf[g][sel + 2]);
                }
            }
        }
    }

    // epilogue: bias + fast GELU, direct float2 stores (sectors fully covered)
    const int tg = lane & 3, gp = lane >> 2;
#pragma unroll
    for (int mf = 0; mf < 4; mf++) {
#pragma unroll
        for (int nf = 0; nf < 8; nf++) {
            int row = m0 + warp_m * 64 + mf * 16 + gp;
            int col = n0 + warp_n * 64 + nf * 8 + tg * 2;
            float2 bv = *reinterpret_cast<const float2*>(bias + col);
            float2 o0, o1;
            o0.x = gelu_fast(acc[mf][nf][0] + bv.x);
            o0.y = gelu_fast(acc[mf][nf][1] + bv.y);
            o1.x = gelu_fast(acc[mf][nf][2] + bv.x);
            o1.y = gelu_fast(acc[mf][nf][3] + bv.y);
            *reinterpret_cast<float2*>(out + (size_t)row * NDIM + col) = o0;
            *reinterpret_cast<float2*>(out + (size_t)(row + 8) * NDIM + col) = o1;
        }
    }
#undef LOAD_STAGE
}

// ---------------------------------------------------------------------------
// Launch
// ---------------------------------------------------------------------------
extern "C" void kernel_launch(void* const* d_in, const int* in_sizes, int n_in,
                              void* d_out, int out_size) {
    const float* x     = (const float*)d_in[0];
    const float* gamma = (const float*)d_in[1];
    const float* beta  = (const float*)d_in[2];
    const float* W     = (const float*)d_in[3];
    const float* b     = (const float*)d_in[4];
    float* out = (float*)d_out;

    prepass_kernel<<<LN_BLOCKS + WC_BLOCKS, 256>>>(x, gamma, beta, W);

    cudaFuncSetAttribute(gemm_kernel,
                         cudaFuncAttributeMaxDynamicSharedMemorySize, SMEM_TOTAL);
    dim3 grid(NDIM / N_TILE, ROWS_TOTAL / M_TILE);   // (12, 392)
    gemm_kernel<<<grid, 128, SMEM_TOTAL>>>(b, out);
}

// round 15
// speedup vs baseline: 1.5433x; 1.5433x over previous
#include <cuda_runtime.h>
#include <cuda_fp16.h>
#include <cstdint>

// ---------------------------------------------------------------------------
// Problem constants
// ---------------------------------------------------------------------------
#define ROWS_TOTAL 50176        // 256*14*14
#define KDIM       384
#define NDIM       1536
#define M_TILE     128
#define N_TILE     128
#define K_CHUNK    32
#define NUM_KC     (KDIM / K_CHUNK)   // 12
#define NUM_KF     (KDIM / 16)        // 24 k-fragments
#define STAGES     4
#define LN_EPS     1e-6f

// fp16 scratch (no cudaMalloc allowed -> __device__ globals)
__device__ __half g_xh[(size_t)ROWS_TOTAL * KDIM];   // LN-applied X, fp16
// W pre-packed into m16n8k16 B-fragment layout:
// [np (n/16 pair) 0..95][kf (k/16) 0..23][lane 0..31] -> uint4 {b0,b1,b0',b1'}
__device__ uint4 g_wf[(NDIM / 16) * NUM_KF * 32];    // 96*24*32 = 73728 (1.18MB)

// ---------------------------------------------------------------------------
// Inline PTX (baseline features only: ldmatrix / mma.sync / cp.async)
// ---------------------------------------------------------------------------
__device__ __forceinline__ uint32_t smem_u32(const void* p) {
    uint32_t a;
    asm("{ .reg .u64 t; cvta.to.shared.u64 t, %1; cvt.u32.u64 %0, t; }"
        : "=r"(a) : "l"(p));
    return a;
}

#define CP_ASYNC16(saddr, gptr) \
    asm volatile("cp.async.cg.shared.global [%0], [%1], 16;" \
                 :: "r"(saddr), "l"(gptr))

#define CP_COMMIT() asm volatile("cp.async.commit_group;")
#define CP_WAIT(n)  asm volatile("cp.async.wait_group %0;" :: "n"(n))

#define LDSM_X4(r, addr) \
    asm volatile("ldmatrix.sync.aligned.m8n8.x4.shared.b16 {%0,%1,%2,%3}, [%4];" \
                 : "=r"((r)[0]), "=r"((r)[1]), "=r"((r)[2]), "=r"((r)[3]) \
                 : "r"(addr))

#define MMA16816(c, a, b0v, b1v) \
    asm volatile("mma.sync.aligned.m16n8k16.row.col.f32.f16.f16.f32 " \
                 "{%0,%1,%2,%3}, {%4,%5,%6,%7}, {%8,%9}, {%0,%1,%2,%3};" \
                 : "+f"((c)[0]), "+f"((c)[1]), "+f"((c)[2]), "+f"((c)[3]) \
                 : "r"((a)[0]), "r"((a)[1]), "r"((a)[2]), "r"((a)[3]), \
                   "r"(b0v), "r"(b1v))

// ---------------------------------------------------------------------------
// SMEM: A only, per stage [128][40] fp16, 80B padded rows (conflict-free)
// ---------------------------------------------------------------------------
#define ROW_B      80
#define STAGE_B    (M_TILE * ROW_B)       // 10240
#define SMEM_TOTAL (STAGES * STAGE_B)     // 40960 -> 2 CTAs/SM easily

// Fast GELU: v * sigmoid(1.59577(v + 0.044715 v^3)) — branch-free, 2 MUFU.
__device__ __forceinline__ float gelu_fast(float v) {
    float t = v * v;
    float z = 1.5957691216f * v * fmaf(0.044715f, t, 1.0f);
    float e = __expf(-z);
    return __fdividef(v, 1.0f + e);
}

__device__ __forceinline__ uint32_t pack2(float a, float b) {
    return (uint32_t)__half_as_ushort(__float2half_rn(a))
         | ((uint32_t)__half_as_ushort(__float2half_rn(b)) << 16);
}

// ---------------------------------------------------------------------------
// Kernel 1: fused prepass.
//   Blocks [0, LN_BLOCKS): LayerNorm -> fp16 X.
//   Blocks [LN_BLOCKS, +WF_BLOCKS): W fp32 -> fragment-packed fp16 (g_wf).
// ---------------------------------------------------------------------------
#define LN_BLOCKS  (ROWS_TOTAL / 8)            // 6272
#define WF_WORDS   ((NDIM / 16) * NUM_KF * 32) // 73728
#define WF_BLOCKS  (WF_WORDS / 256)            // 288

__global__ __launch_bounds__(256) void prepass_kernel(
    const float* __restrict__ x,
    const float* __restrict__ gamma,
    const float* __restrict__ beta,
    const float* __restrict__ W)
{
    if (blockIdx.x >= LN_BLOCKS) {
        int id   = (blockIdx.x - LN_BLOCKS) * 256 + threadIdx.x;  // 0..73727
        int lane = id & 31;
        int t    = id >> 5;             // 0..2303
        int kf   = t % NUM_KF;
        int np   = t / NUM_KF;          // 0..95
        int nA   = np * 16 + (lane >> 2);
        int nB   = nA + 8;
        int k    = kf * 16 + (lane & 3) * 2;
        const float* wA = W + (size_t)nA * KDIM + k;
        const float* wB = W + (size_t)nB * KDIM + k;
        uint4 v;
        v.x = pack2(wA[0], wA[1]);      // b0  (k, k+1)   for n-frag A
        v.y = pack2(wA[8], wA[9]);      // b1  (k+8, k+9) for n-frag A
        v.z = pack2(wB[0], wB[1]);      // b0  for n-frag B
        v.w = pack2(wB[8], wB[9]);      // b1  for n-frag B
        g_wf[id] = v;
        return;
    }

    int row  = blockIdx.x * 8 + (threadIdx.x >> 5);
    int lane = threadIdx.x & 31;
    const float4* xr = reinterpret_cast<const float4*>(x + (size_t)row * KDIM);

    float4 v[3];
    float s = 0.f, ss = 0.f;
#pragma unroll
    for (int i = 0; i < 3; i++) {
        v[i] = xr[lane + i * 32];
        s  += v[i].x + v[i].y + v[i].z + v[i].w;
        ss += v[i].x * v[i].x + v[i].y * v[i].y + v[i].z * v[i].z + v[i].w * v[i].w;
    }
#pragma unroll
    for (int o = 16; o > 0; o >>= 1) {
        s  += __shfl_xor_sync(0xffffffffu, s, o);
        ss += __shfl_xor_sync(0xffffffffu, ss, o);
    }
    float mu  = s * (1.0f / KDIM);
    float var = ss * (1.0f / KDIM) - mu * mu;
    float rs  = rsqrtf(var + LN_EPS);

#pragma unroll
    for (int i = 0; i < 3; i++) {
        int col = (lane + i * 32) * 4;
        float4 gv = *reinterpret_cast<const float4*>(gamma + col);
        float4 bv = *reinterpret_cast<const float4*>(beta + col);
        float n0 = fmaf(v[i].x - mu, rs * gv.x, bv.x);
        float n1 = fmaf(v[i].y - mu, rs * gv.y, bv.y);
        float n2 = fmaf(v[i].z - mu, rs * gv.z, bv.z);
        float n3 = fmaf(v[i].w - mu, rs * gv.w, bv.w);

        __half2* p = reinterpret_cast<__half2*>(g_xh + (size_t)row * KDIM + col);
        p[0] = __half2(__float2half_rn(n0), __float2half_rn(n1));
        p[1] = __half2(__float2half_rn(n2), __float2half_rn(n3));
    }
}

// ---------------------------------------------------------------------------
// Kernel 2: fp16 GEMM + bias + fast GELU
// CTA tile 128x128; 8 warps (4M x 2N), warp tile 32x64.
// A via 4-stage cp.async smem pipeline (smem holds ONLY A).
// B fragments loaded global->register (LDG.128 from pre-packed g_wf, L2-hot),
// software-prefetched one k16-step ahead. No B smem traffic, no B LDSM.
// ---------------------------------------------------------------------------
__global__ __launch_bounds__(256, 2) void gemm_kernel(
    const float* __restrict__ bias,
    float* __restrict__ out)
{
    extern __shared__ char smem[];
    const uint32_t smem_base = smem_u32(smem);

    const int tid    = threadIdx.x;
    const int wid    = tid >> 5;
    const int lane   = tid & 31;
    const int warp_m = wid & 3;          // 0..3 (32-row quarters)
    const int warp_n = wid >> 2;         // 0..1 (64-col halves)
    const int lrow   = lane & 15;
    const int lsel   = lane >> 4;

    const int n0 = blockIdx.x * N_TILE;  // n fastest -> X-tile L2 reuse
    const int m0 = blockIdx.y * M_TILE;

    // --- A loader: 512 x 16B chunks per stage, 2 per thread ---
    const int ldr = tid >> 2;            // 0..63  (x2 rows via +64)
    const int ldc = tid & 3;
    const __half* pa = g_xh + (size_t)(m0 + ldr) * KDIM + ldc * 8;
    const uint32_t soA = (uint32_t)(ldr * ROW_B + ldc * 16);

#define LOAD_STAGE(sb, k0)                                             \
    do {                                                               \
        CP_ASYNC16((sb) + soA,            pa + (k0));                  \
        CP_ASYNC16((sb) + soA + 64*ROW_B, pa + 64*KDIM + (k0));        \
    } while (0)

    // --- hoisted A ldmatrix base offsets ---
    uint32_t a_base[2];
#pragma unroll
    for (int mf = 0; mf < 2; mf++)
        a_base[mf] = (uint32_t)((warp_m * 32 + mf * 16 + lrow) * ROW_B + lsel * 16);

    // --- B fragment pointer: this warp covers n-frag pairs warp_n*4 .. +3 ---
    const uint4* pw = g_wf + ((size_t)(n0 / 16 + warp_n * 4) * NUM_KF) * 32 + lane;

    // prologue: prefetch STAGES-1 A stages
#pragma unroll
    for (int s = 0; s < STAGES - 1; s++) {
        LOAD_STAGE(smem_base + s * STAGE_B, s * K_CHUNK);
        CP_COMMIT();
    }

    float acc[2][8][4];
#pragma unroll
    for (int a = 0; a < 2; a++)
#pragma unroll
        for (int b = 0; b < 8; b++)
#pragma unroll
            for (int c = 0; c < 4; c++) acc[a][b][c] = 0.f;

    // preload B fragments for (kc=0, ks=0): kf = 0
    uint4 bf0[4], bf1[4];
#pragma unroll
    for (int p = 0; p < 4; p++)
        bf0[p] = __ldg(&pw[(size_t)(p * NUM_KF + 0) * 32]);

#define DO_MMAS(af, bf)                                                     \
    do {                                                                    \
        _Pragma("unroll")                                                   \
        for (int mf = 0; mf < 2; mf++) {                                    \
            _Pragma("unroll")                                               \
            for (int p = 0; p < 4; p++) {                                   \
                MMA16816(acc[mf][p*2],   (af)[mf], (bf)[p].x, (bf)[p].y);   \
                MMA16816(acc[mf][p*2+1], (af)[mf], (bf)[p].z, (bf)[p].w);   \
            }                                                               \
        }                                                                   \
    } while (0)

#pragma unroll
    for (int kc = 0; kc < NUM_KC; kc++) {
        CP_WAIT(STAGES - 2);
        __syncthreads();

        if (kc + STAGES - 1 < NUM_KC)
            LOAD_STAGE(smem_base + ((kc + STAGES - 1) % STAGES) * STAGE_B,
                       (kc + STAGES - 1) * K_CHUNK);
        CP_COMMIT();

        const uint32_t st = smem_base + (kc % STAGES) * STAGE_B;

        // ---- ks = 0: prefetch B(ks=1), LDSM A(ks=0), MMAs on bf0 ----
        {
            const int kf1 = kc * 2 + 1;
#pragma unroll
            for (int p = 0; p < 4; p++)
                bf1[p] = __ldg(&pw[(size_t)(p * NUM_KF + kf1) * 32]);
            uint32_t af[2][4];
            LDSM_X4(af[0], st + a_base[0]);
            LDSM_X4(af[1], st + a_base[1]);
            DO_MMAS(af, bf0);
        }

        // ---- ks = 1: prefetch B(next kc, ks=0), LDSM A(ks=1), MMAs on bf1 ----
        {
            if (kc + 1 < NUM_KC) {
                const int kf0 = (kc + 1) * 2;
#pragma unroll
                for (int p = 0; p < 4; p++)
                    bf0[p] = __ldg(&pw[(size_t)(p * NUM_KF + kf0) * 32]);
            }
            uint32_t af[2][4];
            LDSM_X4(af[0], st + a_base[0] + 32);
            LDSM_X4(af[1], st + a_base[1] + 32);
            DO_MMAS(af, bf1);
        }
    }

    // epilogue: bias + fast GELU, direct float2 stores (sectors fully covered)
    const int tg = lane & 3, gp = lane >> 2;
#pragma unroll
    for (int mf = 0; mf < 2; mf++) {
#pragma unroll
        for (int nf = 0; nf < 8; nf++) {
            int row = m0 + warp_m * 32 + mf * 16 + gp;
            int col = n0 + warp_n * 64 + nf * 8 + tg * 2;
            float2 bv = *reinterpret_cast<const float2*>(bias + col);
            float2 o0, o1;
            o0.x = gelu_fast(acc[mf][nf][0] + bv.x);
            o0.y = gelu_fast(acc[mf][nf][1] + bv.y);
            o1.x = gelu_fast(acc[mf][nf][2] + bv.x);
            o1.y = gelu_fast(acc[mf][nf][3] + bv.y);
            *reinterpret_cast<float2*>(out + (size_t)row * NDIM + col) = o0;
            *reinterpret_cast<float2*>(out + (size_t)(row + 8) * NDIM + col) = o1;
        }
    }
#undef LOAD_STAGE
#undef DO_MMAS
}

// ---------------------------------------------------------------------------
// Launch
// ---------------------------------------------------------------------------
extern "C" void kernel_launch(void* const* d_in, const int* in_sizes, int n_in,
                              void* d_out, int out_size) {
    const float* x     = (const float*)d_in[0];
    const float* gamma = (const float*)d_in[1];
    const float* beta  = (const float*)d_in[2];
    const float* W     = (const float*)d_in[3];
    const float* b     = (const float*)d_in[4];
    float* out = (float*)d_out;

    prepass_kernel<<<LN_BLOCKS + WF_BLOCKS, 256>>>(x, gamma, beta, W);

    cudaFuncSetAttribute(gemm_kernel,
                         cudaFuncAttributeMaxDynamicSharedMemorySize, SMEM_TOTAL);
    dim3 grid(NDIM / N_TILE, ROWS_TOTAL / M_TILE);   // (12, 392)
    gemm_kernel<<<grid, 256, SMEM_TOTAL>>>(b, out);
}

// round 16
// speedup vs baseline: 1.6482x; 1.0680x over previous
#include <cuda_runtime.h>
#include <cuda_fp16.h>
#include <cstdint>

// ---------------------------------------------------------------------------
// Problem constants
// ---------------------------------------------------------------------------
#define ROWS_TOTAL 50176        // 256*14*14
#define KDIM       384
#define NDIM       1536
#define M_TILE     128
#define N_TILE     128
#define NUM_KF     (KDIM / 16)        // 24 k-fragments
#define LN_EPS     1e-6f

// Fragment-packed operands (no cudaMalloc -> __device__ globals).
// A: [mfrag 0..3135][kf 0..23][lane 0..31] -> uint4 {a0,a1,a2,a3}  (38.5MB)
// B: [npair 0..95][kf 0..23][lane 0..31]  -> uint4 {b0,b1,b0',b1'} (1.18MB)
__device__ uint4 g_xf[(ROWS_TOTAL / 16) * NUM_KF * 32];
__device__ uint4 g_wf[(NDIM / 16) * NUM_KF * 32];

// ---------------------------------------------------------------------------
// Inline PTX
// ---------------------------------------------------------------------------
#define MMA_U4(c, a4, b0v, b1v) \
    asm volatile("mma.sync.aligned.m16n8k16.row.col.f32.f16.f16.f32 " \
                 "{%0,%1,%2,%3}, {%4,%5,%6,%7}, {%8,%9}, {%0,%1,%2,%3};" \
                 : "+f"((c)[0]), "+f"((c)[1]), "+f"((c)[2]), "+f"((c)[3]) \
                 : "r"((a4).x), "r"((a4).y), "r"((a4).z), "r"((a4).w), \
                   "r"(b0v), "r"(b1v))

// Fast GELU: v * sigmoid(1.59577(v + 0.044715 v^3)) — branch-free, 2 MUFU.
__device__ __forceinline__ float gelu_fast(float v) {
    float t = v * v;
    float z = 1.5957691216f * v * fmaf(0.044715f, t, 1.0f);
    float e = __expf(-z);
    return __fdividef(v, 1.0f + e);
}

__device__ __forceinline__ uint32_t pack2(float a, float b) {
    return (uint32_t)__half_as_ushort(__float2half_rn(a))
         | ((uint32_t)__half_as_ushort(__float2half_rn(b)) << 16);
}

// ---------------------------------------------------------------------------
// Kernel 1: fused prepass (512-thread blocks).
//  Blocks [0, LN_BLOCKS): LayerNorm 16 rows -> one A m-fragment row of g_xf.
//  Blocks [LN_BLOCKS, +WF_BLOCKS): W fp32 -> B-fragment pack (g_wf).
// ---------------------------------------------------------------------------
#define LN_BLOCKS  (ROWS_TOTAL / 16)           // 3136
#define WF_WORDS   ((NDIM / 16) * NUM_KF * 32) // 73728
#define WF_BLOCKS  (WF_WORDS / 512)            // 144
#define SROW       200                         // smem row stride in words

__global__ __launch_bounds__(512) void prepass_kernel(
    const float* __restrict__ x,
    const float* __restrict__ gamma,
    const float* __restrict__ beta,
    const float* __restrict__ W)
{
    if (blockIdx.x >= LN_BLOCKS) {
        // ---- W fragment pack ----
        int id   = (blockIdx.x - LN_BLOCKS) * 512 + threadIdx.x;  // 0..73727
        int lane = id & 31;
        int t    = id >> 5;
        int kf   = t % NUM_KF;
        int np   = t / NUM_KF;          // 0..95
        int nA   = np * 16 + (lane >> 2);
        int nB   = nA + 8;
        int k    = kf * 16 + (lane & 3) * 2;
        const float* wA = W + (size_t)nA * KDIM + k;
        const float* wB = W + (size_t)nB * KDIM + k;
        uint4 v;
        v.x = pack2(wA[0], wA[1]);
        v.y = pack2(wA[8], wA[9]);
        v.z = pack2(wB[0], wB[1]);
        v.w = pack2(wB[8], wB[9]);
        g_wf[id] = v;
        return;
    }

    // ---- LayerNorm: 16 warps, one row each; stage fp16 rows in smem ----
    __shared__ uint32_t sx[16 * SROW];
    const int wid  = threadIdx.x >> 5;
    const int lane = threadIdx.x & 31;
    const int row  = blockIdx.x * 16 + wid;
    const float4* xr = reinterpret_cast<const float4*>(x + (size_t)row * KDIM);

    float4 v[3];
    float s = 0.f, ss = 0.f;
#pragma unroll
    for (int i = 0; i < 3; i++) {
        v[i] = xr[lane + i * 32];
        s  += v[i].x + v[i].y + v[i].z + v[i].w;
        ss += v[i].x * v[i].x + v[i].y * v[i].y + v[i].z * v[i].z + v[i].w * v[i].w;
    }
#pragma unroll
    for (int o = 16; o > 0; o >>= 1) {
        s  += __shfl_xor_sync(0xffffffffu, s, o);
        ss += __shfl_xor_sync(0xffffffffu, ss, o);
    }
    float mu  = s * (1.0f / KDIM);
    float var = ss * (1.0f / KDIM) - mu * mu;
    float rs  = rsqrtf(var + LN_EPS);

#pragma unroll
    for (int i = 0; i < 3; i++) {
        int col = (lane + i * 32) * 4;
        float4 gv = *reinterpret_cast<const float4*>(gamma + col);
        float4 bv = *reinterpret_cast<const float4*>(beta + col);
        float n0 = fmaf(v[i].x - mu, rs * gv.x, bv.x);
        float n1 = fmaf(v[i].y - mu, rs * gv.y, bv.y);
        float n2 = fmaf(v[i].z - mu, rs * gv.z, bv.z);
        float n3 = fmaf(v[i].w - mu, rs * gv.w, bv.w);
        sx[wid * SROW + (lane + i * 32) * 2]     = pack2(n0, n1);
        sx[wid * SROW + (lane + i * 32) * 2 + 1] = pack2(n2, n3);
    }
    __syncthreads();

    // ---- A fragment pack: this block = m-fragment row blockIdx.x ----
    // lane l of fragment (kf): a0=(r, k..k+1) a1=(r+8,..) a2=(r,k+8..) a3=(r+8,k+8..)
    // r = l>>2, k = kf*16 + (l&3)*2
#pragma unroll
    for (int idx = threadIdx.x; idx < NUM_KF * 32; idx += 512) {
        int kf = idx >> 5;
        int l  = idx & 31;
        int r  = l >> 2;
        int w0 = kf * 8 + (l & 3);   // word offset of (k,k+1) within row
        uint4 o;
        o.x = sx[r * SROW + w0];
        o.y = sx[(r + 8) * SROW + w0];
        o.z = sx[r * SROW + w0 + 4];
        o.w = sx[(r + 8) * SROW + w0 + 4];
        g_xf[((size_t)blockIdx.x * NUM_KF + kf) * 32 + l] = o;
    }
}

// ---------------------------------------------------------------------------
// Kernel 2: fp16 GEMM + bias + fast GELU — ZERO shared memory, ZERO barriers.
// CTA tile 128x128; 8 warps (4M x 2N), warp tile 32x64.
// Both operands stream as pre-packed MMA fragments via LDG.128 (L2/L1-hot),
// double-buffered one k16-step ahead.
// ---------------------------------------------------------------------------
__global__ __launch_bounds__(256, 2) void gemm_kernel(
    const float* __restrict__ bias,
    float* __restrict__ out)
{
    const int tid    = threadIdx.x;
    const int wid    = tid >> 5;
    const int lane   = tid & 31;
    const int warp_m = wid & 3;          // 0..3 (32-row quarters)
    const int warp_n = wid >> 2;         // 0..1 (64-col halves)

    const int n0 = blockIdx.x * N_TILE;  // n fastest -> A-fragment L2 reuse
    const int m0 = blockIdx.y * M_TILE;

    // fragment base pointers (stride between frag rows = NUM_KF*32 uint4)
    const uint4* pA = g_xf + ((size_t)(m0 / 16) + warp_m * 2) * (NUM_KF * 32) + lane;
    const uint4* pB = g_wf + ((size_t)(n0 / 16) + warp_n * 4) * (NUM_KF * 32) + lane;

#define LDF(af, bf, kf)                                            \
    do {                                                           \
        (af)[0] = __ldg(pA + (0 * NUM_KF + (kf)) * 32);            \
        (af)[1] = __ldg(pA + (1 * NUM_KF + (kf)) * 32);            \
        (bf)[0] = __ldg(pB + (0 * NUM_KF + (kf)) * 32);            \
        (bf)[1] = __ldg(pB + (1 * NUM_KF + (kf)) * 32);            \
        (bf)[2] = __ldg(pB + (2 * NUM_KF + (kf)) * 32);            \
        (bf)[3] = __ldg(pB + (3 * NUM_KF + (kf)) * 32);            \
    } while (0)

#define MMAS(af, bf)                                                      \
    do {                                                                  \
        _Pragma("unroll")                                                 \
        for (int mf = 0; mf < 2; mf++) {                                  \
            _Pragma("unroll")                                             \
            for (int p = 0; p < 4; p++) {                                 \
                MMA_U4(acc[mf][p * 2],     (af)[mf], (bf)[p].x, (bf)[p].y); \
                MMA_U4(acc[mf][p * 2 + 1], (af)[mf], (bf)[p].z, (bf)[p].w); \
            }                                                             \
        }                                                                 \
    } while (0)

    float acc[2][8][4];
#pragma unroll
    for (int a = 0; a < 2; a++)
#pragma unroll
        for (int b = 0; b < 8; b++)
#pragma unroll
            for (int c = 0; c < 4; c++) acc[a][b][c] = 0.f;

    uint4 afA[2], bfA[4], afB[2], bfB[4];
    LDF(afA, bfA, 0);

#pragma unroll
    for (int kf = 0; kf < NUM_KF; kf += 2) {
        if (kf + 1 < NUM_KF) LDF(afB, bfB, kf + 1);
        MMAS(afA, bfA);
        if (kf + 2 < NUM_KF) LDF(afA, bfA, kf + 2);
        MMAS(afB, bfB);
    }

    // epilogue: bias + fast GELU, direct float2 stores (sectors fully covered)
    const int tg = lane & 3, gp = lane >> 2;
#pragma unroll
    for (int mf = 0; mf < 2; mf++) {
#pragma unroll
        for (int nf = 0; nf < 8; nf++) {
            int row = m0 + warp_m * 32 + mf * 16 + gp;
            int col = n0 + warp_n * 64 + nf * 8 + tg * 2;
            float2 bv = *reinterpret_cast<const float2*>(bias + col);
            float2 o0, o1;
            o0.x = gelu_fast(acc[mf][nf][0] + bv.x);
            o0.y = gelu_fast(acc[mf][nf][1] + bv.y);
            o1.x = gelu_fast(acc[mf][nf][2] + bv.x);
            o1.y = gelu_fast(acc[mf][nf][3] + bv.y);
            *reinterpret_cast<float2*>(out + (size_t)row * NDIM + col) = o0;
            *reinterpret_cast<float2*>(out + (size_t)(row + 8) * NDIM + col) = o1;
        }
    }
#undef LDF
#undef MMAS
}

// ---------------------------------------------------------------------------
// Launch
// ---------------------------------------------------------------------------
extern "C" void kernel_launch(void* const* d_in, const int* in_sizes, int n_in,
                              void* d_out, int out_size) {
    const float* x     = (const float*)d_in[0];
    const float* gamma = (const float*)d_in[1];
    const float* beta  = (const float*)d_in[2];
    const float* W     = (const float*)d_in[3];
    const float* b     = (const float*)d_in[4];
    float* out = (float*)d_out;

    prepass_kernel<<<LN_BLOCKS + WF_BLOCKS, 512>>>(x, gamma, beta, W);

    dim3 grid(NDIM / N_TILE, ROWS_TOTAL / M_TILE);   // (12, 392)
    gemm_kernel<<<grid, 256>>>(b, out);
}